// round 4
// baseline (speedup 1.0000x reference)
#include <cuda_runtime.h>
#include <cuda_bf16.h>

#define Nn   50000
#define Ee   800000
#define Rr   10
#define Bb   4
#define Dd   64   // D_IN == D_OUT == 64

// Scratch (no allocation allowed -> __device__ globals).
// W_dev: [R+1][64][64], slot R = self-loop weight.
// xr_buf: [R][N][64] = 128 MB.
__device__ __align__(16) float W_dev[(Rr + 1) * Dd * Dd];
__device__ __align__(16) float xr_buf[(size_t)Rr * Nn * Dd];

// ---------------------------------------------------------------------------
// K1: basis combine  W[r] = sum_b w_comp[r,b] * weight[b];  W[R] = self_loop
// ---------------------------------------------------------------------------
__global__ void k_basis(const float* __restrict__ weight,
                        const float* __restrict__ w_comp,
                        const float* __restrict__ selfw) {
    int idx = blockIdx.x * blockDim.x + threadIdx.x;   // over (R+1)*4096
    if (idx < Rr * Dd * Dd) {
        int r  = idx >> 12;          // /4096
        int io = idx & 4095;
        float s = 0.f;
#pragma unroll
        for (int b = 0; b < Bb; b++)
            s += w_comp[r * Bb + b] * weight[b * Dd * Dd + io];
        W_dev[idx] = s;
    } else if (idx < (Rr + 1) * Dd * Dd) {
        W_dev[idx] = selfw[idx - Rr * Dd * Dd];
    }
}

// ---------------------------------------------------------------------------
// K2: per-relation GEMM. blockIdx.y = relation r (r==R -> self-loop into d_out).
// Tile: 128 nodes x 64 cols, K=64. 256 threads, 8x4 register tile per thread.
// ---------------------------------------------------------------------------
#define SLDA 68   // padded row stride for As (multiple of 4 -> float4 aligned)

__global__ __launch_bounds__(256) void k_gemm(const float* __restrict__ feat,
                                              float* __restrict__ d_out) {
    const int r  = blockIdx.y;
    const int nb = blockIdx.x * 128;

    __shared__ __align__(16) float As[128 * SLDA];  // As[m][k]
    __shared__ __align__(16) float Bs[64 * 64];     // Bs[k][n]

    const int tid = threadIdx.x;

    // Load W[r] (16 KB) coalesced
    const float4* Wsrc = (const float4*)(W_dev + r * Dd * Dd);
    for (int i = tid; i < 1024; i += 256)
        ((float4*)Bs)[i] = Wsrc[i];

    // Load feat tile [128 x 64], coalesced, zero-pad past N
#pragma unroll
    for (int i = 0; i < 8; i++) {
        int lin = tid + 256 * i;          // 0..2047
        int m   = lin >> 4;               // 0..127
        int k4  = (lin & 15) << 2;        // 0,4,...,60
        int node = nb + m;
        float4 v = make_float4(0.f, 0.f, 0.f, 0.f);
        if (node < Nn) v = *(const float4*)(feat + node * Dd + k4);
        *(float4*)(As + m * SLDA + k4) = v;
    }
    __syncthreads();

    const int tx = tid & 15;    // col group: cols 4*tx .. 4*tx+3
    const int ty = tid >> 4;    // row group: rows 8*ty .. 8*ty+7

    float acc[8][4];
#pragma unroll
    for (int i = 0; i < 8; i++)
#pragma unroll
        for (int j = 0; j < 4; j++) acc[i][j] = 0.f;

#pragma unroll
    for (int k = 0; k < 64; k += 4) {
        float4 b0 = *(const float4*)(Bs + (k + 0) * 64 + 4 * tx);
        float4 b1 = *(const float4*)(Bs + (k + 1) * 64 + 4 * tx);
        float4 b2 = *(const float4*)(Bs + (k + 2) * 64 + 4 * tx);
        float4 b3 = *(const float4*)(Bs + (k + 3) * 64 + 4 * tx);
#pragma unroll
        for (int i = 0; i < 8; i++) {
            float4 a = *(const float4*)(As + (8 * ty + i) * SLDA + k);
            acc[i][0] = fmaf(a.x, b0.x, acc[i][0]);
            acc[i][1] = fmaf(a.x, b0.y, acc[i][1]);
            acc[i][2] = fmaf(a.x, b0.z, acc[i][2]);
            acc[i][3] = fmaf(a.x, b0.w, acc[i][3]);
            acc[i][0] = fmaf(a.y, b1.x, acc[i][0]);
            acc[i][1] = fmaf(a.y, b1.y, acc[i][1]);
            acc[i][2] = fmaf(a.y, b1.z, acc[i][2]);
            acc[i][3] = fmaf(a.y, b1.w, acc[i][3]);
            acc[i][0] = fmaf(a.z, b2.x, acc[i][0]);
            acc[i][1] = fmaf(a.z, b2.y, acc[i][1]);
            acc[i][2] = fmaf(a.z, b2.z, acc[i][2]);
            acc[i][3] = fmaf(a.z, b2.w, acc[i][3]);
            acc[i][0] = fmaf(a.w, b3.x, acc[i][0]);
            acc[i][1] = fmaf(a.w, b3.y, acc[i][1]);
            acc[i][2] = fmaf(a.w, b3.z, acc[i][2]);
            acc[i][3] = fmaf(a.w, b3.w, acc[i][3]);
        }
    }

    float* outbase = (r < Rr) ? (xr_buf + (size_t)r * Nn * Dd) : d_out;
#pragma unroll
    for (int i = 0; i < 8; i++) {
        int node = nb + 8 * ty + i;
        if (node < Nn) {
            float4 v = make_float4(acc[i][0], acc[i][1], acc[i][2], acc[i][3]);
            *(float4*)(outbase + (size_t)node * Dd + 4 * tx) = v;
        }
    }
}

// ---------------------------------------------------------------------------
// K3: edge scatter. 16 threads per edge, each covers 4 output columns.
// out[dst] += norm * xr[etype][src]   via vectorized red.global.add.v4.f32
// ---------------------------------------------------------------------------
__device__ __forceinline__ void red_add_v4(float* addr, float4 v) {
    asm volatile("red.global.add.v4.f32 [%0], {%1,%2,%3,%4};"
                 :: "l"(addr), "f"(v.x), "f"(v.y), "f"(v.z), "f"(v.w)
                 : "memory");
}

__global__ __launch_bounds__(256) void k_scatter(const int* __restrict__ src,
                                                 const int* __restrict__ dst,
                                                 const int* __restrict__ etype,
                                                 const float* __restrict__ norm,
                                                 float* __restrict__ out) {
    long long gt = (long long)blockIdx.x * 256 + threadIdx.x;
    int e = (int)(gt >> 4);
    if (e >= Ee) return;
    int c = ((int)gt & 15) << 2;

    int   s  = __ldg(src + e);
    int   d  = __ldg(dst + e);
    int   r  = __ldg(etype + e);
    float nm = __ldg(norm + e);

    const float4 v = *(const float4*)(xr_buf + ((size_t)r * Nn + s) * Dd + c);
    float4 m = make_float4(v.x * nm, v.y * nm, v.z * nm, v.w * nm);
    red_add_v4(out + (size_t)d * Dd + c, m);
}

// ---------------------------------------------------------------------------
// K4: ReLU in place
// ---------------------------------------------------------------------------
__global__ __launch_bounds__(256) void k_relu(float* __restrict__ out) {
    int i = blockIdx.x * blockDim.x + threadIdx.x;   // over N*64/4 float4s
    if (i < Nn * Dd / 4) {
        float4 v = ((float4*)out)[i];
        v.x = fmaxf(v.x, 0.f);
        v.y = fmaxf(v.y, 0.f);
        v.z = fmaxf(v.z, 0.f);
        v.w = fmaxf(v.w, 0.f);
        ((float4*)out)[i] = v;
    }
}

// ---------------------------------------------------------------------------
// Inputs (metadata order): feat, src, dst, etype, norm, weight, w_comp,
//                          self_loop_weight.  Output: float [N, 64].
// ---------------------------------------------------------------------------
extern "C" void kernel_launch(void* const* d_in, const int* in_sizes, int n_in,
                              void* d_out, int out_size) {
    const float* feat   = (const float*)d_in[0];
    const int*   src    = (const int*)d_in[1];
    const int*   dst    = (const int*)d_in[2];
    const int*   etype  = (const int*)d_in[3];
    const float* norm   = (const float*)d_in[4];
    const float* weight = (const float*)d_in[5];
    const float* w_comp = (const float*)d_in[6];
    const float* selfw  = (const float*)d_in[7];
    float* out = (float*)d_out;

    // K1: basis combine  ((R+1)*4096 = 45056 elements)
    k_basis<<<176, 256>>>(weight, w_comp, selfw);

    // K2: 11 relation GEMMs (slot R -> d_out, pre-ReLU, fully overwrites out)
    dim3 g2((Nn + 127) / 128, Rr + 1);
    k_gemm<<<g2, 256>>>(feat, out);

    // K3: edge scatter-add
    int n3 = (int)(((long long)Ee * 16 + 255) / 256);
    k_scatter<<<n3, 256>>>(src, dst, etype, norm, out);

    // K4: ReLU
    k_relu<<<(Nn * Dd / 4 + 255) / 256, 256>>>(out);
}

// round 6
// speedup vs baseline: 1.3284x; 1.3284x over previous
#include <cuda_runtime.h>
#include <cuda_bf16.h>
#include <cstdint>

#define Nn   50000
#define Ee   800000
#define Rr   10
#define Bb   4
#define Dd   64   // D_IN == D_OUT == 64

// Scratch (no allocation allowed -> __device__ globals).
// W_dev: [R+1][64][64] (tf32-rounded bit patterns), slot R = self-loop weight.
// xr_buf: [R][N][64] = 128 MB.
__device__ __align__(16) float W_dev[(Rr + 1) * Dd * Dd];
__device__ __align__(16) float xr_buf[(size_t)Rr * Nn * Dd];

__device__ __forceinline__ uint32_t f32_to_tf32(float f) {
    uint32_t t;
    asm("cvt.rna.tf32.f32 %0, %1;" : "=r"(t) : "f"(f));
    return t;
}

// ---------------------------------------------------------------------------
// K1: basis combine  W[r] = sum_b w_comp[r,b] * weight[b];  W[R] = self_loop
//     Stored tf32-rounded so the GEMM inner loop needs no CVTs for B.
// ---------------------------------------------------------------------------
__global__ void k_basis(const float* __restrict__ weight,
                        const float* __restrict__ w_comp,
                        const float* __restrict__ selfw) {
    int idx = blockIdx.x * blockDim.x + threadIdx.x;   // over (R+1)*4096
    if (idx < Rr * Dd * Dd) {
        int r  = idx >> 12;
        int io = idx & 4095;
        float s = 0.f;
#pragma unroll
        for (int b = 0; b < Bb; b++)
            s += w_comp[r * Bb + b] * weight[b * Dd * Dd + io];
        ((uint32_t*)W_dev)[idx] = f32_to_tf32(s);
    } else if (idx < (Rr + 1) * Dd * Dd) {
        ((uint32_t*)W_dev)[idx] = f32_to_tf32(selfw[idx - Rr * Dd * Dd]);
    }
}

// ---------------------------------------------------------------------------
// K2: per-relation GEMM on tensor cores (mma.sync m16n8k8 tf32).
// CTA: 128 M x 64 N, K=64. 4 warps, warp tile 32M x 64N (2 mfrag x 8 nfrag).
// As[m][k] stride 68, Bs[n][k] stride 68 -> all frag LDS conflict-free.
// blockIdx.y = relation r (r==R -> self-loop straight into d_out, pre-ReLU).
// ---------------------------------------------------------------------------
#define SLD 68
#define GEMM_SMEM ((128 * SLD + 64 * SLD) * 4)   // 52224 bytes

__global__ __launch_bounds__(128) void k_gemm(const float* __restrict__ feat,
                                              float* __restrict__ d_out) {
    extern __shared__ uint32_t sh[];
    uint32_t* As = sh;                 // [128][SLD]
    uint32_t* Bs = sh + 128 * SLD;     // [64][SLD], stored [n][k]

    const int r   = blockIdx.y;
    const int nb  = blockIdx.x * 128;
    const int tid = threadIdx.x;

    // --- Stage Bs = W[r]^T ([n][k]) from tf32-prerounded W_dev, coalesced read ---
    {
        const uint32_t* Wsrc = (const uint32_t*)W_dev + r * Dd * Dd;  // [k][n]
#pragma unroll
        for (int it = 0; it < 32; it++) {
            int idx = tid + it * 128;          // 0..4095
            int k = idx >> 6, n = idx & 63;
            Bs[n * SLD + k] = Wsrc[idx];
        }
    }

    // --- Stage As = tf32(feat tile) [128][k], coalesced float4, zero-pad ---
#pragma unroll
    for (int it = 0; it < 16; it++) {
        int lin = tid + it * 128;              // 0..2047 float4s
        int m   = lin >> 4;
        int k4  = (lin & 15) << 2;
        int node = nb + m;
        float4 v = make_float4(0.f, 0.f, 0.f, 0.f);
        if (node < Nn) v = *(const float4*)(feat + (size_t)node * Dd + k4);
        uint32_t* p = As + m * SLD + k4;
        p[0] = f32_to_tf32(v.x); p[1] = f32_to_tf32(v.y);
        p[2] = f32_to_tf32(v.z); p[3] = f32_to_tf32(v.w);
    }
    __syncthreads();

    const int lane = tid & 31;
    const int warp = tid >> 5;          // 0..3 -> 32-row M slab
    const int g    = lane >> 2;         // groupID 0..7
    const int tig  = lane & 3;          // thread-in-group
    const int mb   = warp * 32;

    float acc[2][8][4];
#pragma unroll
    for (int mf = 0; mf < 2; mf++)
#pragma unroll
        for (int nf = 0; nf < 8; nf++)
#pragma unroll
            for (int j = 0; j < 4; j++) acc[mf][nf][j] = 0.f;

#pragma unroll
    for (int k0 = 0; k0 < 64; k0 += 8) {
        uint32_t a[2][4];
#pragma unroll
        for (int mf = 0; mf < 2; mf++) {
            int row = mb + mf * 16 + g;
            a[mf][0] = As[row * SLD + k0 + tig];
            a[mf][1] = As[(row + 8) * SLD + k0 + tig];
            a[mf][2] = As[row * SLD + k0 + tig + 4];
            a[mf][3] = As[(row + 8) * SLD + k0 + tig + 4];
        }
#pragma unroll
        for (int nf = 0; nf < 8; nf++) {
            uint32_t b0 = Bs[(nf * 8 + g) * SLD + k0 + tig];
            uint32_t b1 = Bs[(nf * 8 + g) * SLD + k0 + tig + 4];
#pragma unroll
            for (int mf = 0; mf < 2; mf++) {
                asm volatile(
                    "mma.sync.aligned.m16n8k8.row.col.f32.tf32.tf32.f32 "
                    "{%0,%1,%2,%3}, {%4,%5,%6,%7}, {%8,%9}, {%0,%1,%2,%3};"
                    : "+f"(acc[mf][nf][0]), "+f"(acc[mf][nf][1]),
                      "+f"(acc[mf][nf][2]), "+f"(acc[mf][nf][3])
                    : "r"(a[mf][0]), "r"(a[mf][1]), "r"(a[mf][2]), "r"(a[mf][3]),
                      "r"(b0), "r"(b1));
            }
        }
    }

    // --- Store: c0/c1 -> row g, cols 2tig/2tig+1; c2/c3 -> row g+8 ---
    float* outbase = (r < Rr) ? (xr_buf + (size_t)r * Nn * Dd) : d_out;
#pragma unroll
    for (int mf = 0; mf < 2; mf++) {
#pragma unroll
        for (int h = 0; h < 2; h++) {
            int row = nb + mb + mf * 16 + g + h * 8;
            if (row < Nn) {
                float* rp = outbase + (size_t)row * Dd + 2 * tig;
#pragma unroll
                for (int nf = 0; nf < 8; nf++) {
                    float2 v = make_float2(acc[mf][nf][2 * h], acc[mf][nf][2 * h + 1]);
                    *(float2*)(rp + nf * 8) = v;
                }
            }
        }
    }
}

// ---------------------------------------------------------------------------
// K3: edge scatter. 16 threads per edge, each covers 4 output columns.
// out[dst] += norm * xr[etype][src]   via vectorized red.global.add.v4.f32
// ---------------------------------------------------------------------------
__device__ __forceinline__ void red_add_v4(float* addr, float4 v) {
    asm volatile("red.global.add.v4.f32 [%0], {%1,%2,%3,%4};"
                 :: "l"(addr), "f"(v.x), "f"(v.y), "f"(v.z), "f"(v.w)
                 : "memory");
}

__global__ __launch_bounds__(256) void k_scatter(const int* __restrict__ src,
                                                 const int* __restrict__ dst,
                                                 const int* __restrict__ etype,
                                                 const float* __restrict__ norm,
                                                 float* __restrict__ out) {
    long long gt = (long long)blockIdx.x * 256 + threadIdx.x;
    int e = (int)(gt >> 4);
    if (e >= Ee) return;
    int c = ((int)gt & 15) << 2;

    int   s  = __ldg(src + e);
    int   d  = __ldg(dst + e);
    int   rr = __ldg(etype + e);
    float nm = __ldg(norm + e);

    const float4 v = *(const float4*)(xr_buf + ((size_t)rr * Nn + s) * Dd + c);
    float4 m = make_float4(v.x * nm, v.y * nm, v.z * nm, v.w * nm);
    red_add_v4(out + (size_t)d * Dd + c, m);
}

// ---------------------------------------------------------------------------
// K4: ReLU in place
// ---------------------------------------------------------------------------
__global__ __launch_bounds__(256) void k_relu(float* __restrict__ out) {
    int i = blockIdx.x * blockDim.x + threadIdx.x;   // over N*64/4 float4s
    if (i < Nn * Dd / 4) {
        float4 v = ((float4*)out)[i];
        v.x = fmaxf(v.x, 0.f);
        v.y = fmaxf(v.y, 0.f);
        v.z = fmaxf(v.z, 0.f);
        v.w = fmaxf(v.w, 0.f);
        ((float4*)out)[i] = v;
    }
}

// ---------------------------------------------------------------------------
// Inputs (metadata order): feat, src, dst, etype, norm, weight, w_comp,
//                          self_loop_weight.  Output: float [N, 64].
// ---------------------------------------------------------------------------
extern "C" void kernel_launch(void* const* d_in, const int* in_sizes, int n_in,
                              void* d_out, int out_size) {
    const float* feat   = (const float*)d_in[0];
    const int*   src    = (const int*)d_in[1];
    const int*   dst    = (const int*)d_in[2];
    const int*   etype  = (const int*)d_in[3];
    const float* norm   = (const float*)d_in[4];
    const float* weight = (const float*)d_in[5];
    const float* w_comp = (const float*)d_in[6];
    const float* selfw  = (const float*)d_in[7];
    float* out = (float*)d_out;

    // Opt-in to >48KB dynamic smem (idempotent; host API, capture-safe)
    cudaFuncSetAttribute(k_gemm, cudaFuncAttributeMaxDynamicSharedMemorySize,
                         GEMM_SMEM);

    // K1: basis combine ((R+1)*4096 = 45056 elements, tf32-rounded)
    k_basis<<<176, 256>>>(weight, w_comp, selfw);

    // K2: 11 relation GEMMs on tensor cores (slot R -> d_out pre-ReLU,
    //     fully overwrites out -> graph replays deterministically)
    dim3 g2((Nn + 127) / 128, Rr + 1);
    k_gemm<<<g2, 128, GEMM_SMEM>>>(feat, out);

    // K3: edge scatter-add
    int n3 = (int)(((long long)Ee * 16 + 255) / 256);
    k_scatter<<<n3, 256>>>(src, dst, etype, norm, out);

    // K4: ReLU
    k_relu<<<(Nn * Dd / 4 + 255) / 256, 256>>>(out);
}